// round 1
// baseline (speedup 1.0000x reference)
#include <cuda_runtime.h>
#include <cuda_bf16.h>
#include <cstdint>

#define T_DIM 200
#define B_DIM 2048
#define H_DIM 128
#define TB (T_DIM*B_DIM)      /* 409600 */
#define BH (B_DIM*H_DIM)      /* 262144 */

// ---------------- scratch (device globals: no allocation allowed) ----------
__device__ float g_mean[BH];
__device__ float g_query[BH];
__device__ __nv_bfloat16 g_wkh[H_DIM*H_DIM];   // w_k^T, hi bf16  [d][h]
__device__ __nv_bfloat16 g_wkl[H_DIM*H_DIM];   // w_k^T, lo bf16  [d][h]
__device__ float g_sim[TB];                    // sim[t][b]

// ---------------------------------------------------------------------------
// K1: session_mean[b][h] = sum_t x[t,b,h] * mask[t,b]
// ---------------------------------------------------------------------------
__global__ void k_mean(const float* __restrict__ x, const float* __restrict__ mask)
{
    int j = blockIdx.x * 256 + threadIdx.x;        // j in [0, BH)
    int b = j >> 7;
    float acc = 0.f;
#pragma unroll 8
    for (int t = 0; t < T_DIM; ++t) {
        float xv = x[(size_t)t * BH + j];
        float mv = __ldg(mask + t * B_DIM + b);
        acc = fmaf(xv, mv, acc);
    }
    g_mean[j] = acc;
}

// ---------------------------------------------------------------------------
// K2a: convert w_k -> transposed bf16 hi/lo pair (done once, tiny)
// ---------------------------------------------------------------------------
__global__ void k_wconv(const float* __restrict__ w_k)
{
    int i = blockIdx.x * 256 + threadIdx.x;        // i in [0, 16384)
    int h = i >> 7, d = i & 127;
    float v = w_k[i];
    __nv_bfloat16 hi = __float2bfloat16(v);
    float r = v - __bfloat162float(hi);
    g_wkh[d * H_DIM + h] = hi;
    g_wkl[d * H_DIM + h] = __float2bfloat16(r);
}

// ---------------------------------------------------------------------------
// K2b: query[b][d] = sum_h mean[b][h] * w_q[h][d]   (8 b's per CTA)
// ---------------------------------------------------------------------------
__global__ void k_query(const float* __restrict__ w_q)
{
    __shared__ float sm[8][128];
    int b0 = blockIdx.x * 8;
    int tid = threadIdx.x;
    for (int i = tid; i < 1024; i += 256)
        sm[i >> 7][i & 127] = g_mean[b0 * H_DIM + i];
    __syncthreads();
    int d = tid & 127, half = tid >> 7;
    float a0 = 0.f, a1 = 0.f, a2 = 0.f, a3 = 0.f;
#pragma unroll 4
    for (int h = 0; h < 128; ++h) {
        float wv = __ldg(w_q + h * H_DIM + d);
        a0 = fmaf(sm[half * 4 + 0][h], wv, a0);
        a1 = fmaf(sm[half * 4 + 1][h], wv, a1);
        a2 = fmaf(sm[half * 4 + 2][h], wv, a2);
        a3 = fmaf(sm[half * 4 + 3][h], wv, a3);
    }
    g_query[(b0 + half * 4 + 0) * H_DIM + d] = a0;
    g_query[(b0 + half * 4 + 1) * H_DIM + d] = a1;
    g_query[(b0 + half * 4 + 2) * H_DIM + d] = a2;
    g_query[(b0 + half * 4 + 3) * H_DIM + d] = a3;
}

// ---------------------------------------------------------------------------
// K3: sim[t][b] = sum_d sigmoid(mask*(x @ w_k)[r][d] + query[b][d]) * w_p[t][d]
//     Tensor-core GEMM via mma.sync bf16, hi/lo split (3 products ~ fp32).
//     One CTA = 128 consecutive rows r = t*B + b (same t), full N=K=128.
// ---------------------------------------------------------------------------
__device__ __forceinline__ void ldsm4(unsigned &r0, unsigned &r1,
                                      unsigned &r2, unsigned &r3, unsigned addr)
{
    asm volatile("ldmatrix.sync.aligned.m8n8.x4.shared.b16 {%0,%1,%2,%3}, [%4];"
                 : "=r"(r0), "=r"(r1), "=r"(r2), "=r"(r3) : "r"(addr));
}
__device__ __forceinline__ void mma_bf16(float *c, const unsigned *a,
                                         unsigned b0, unsigned b1)
{
    asm volatile("mma.sync.aligned.m16n8k16.row.col.f32.bf16.bf16.f32 "
                 "{%0,%1,%2,%3},{%4,%5,%6,%7},{%8,%9},{%0,%1,%2,%3};"
                 : "+f"(c[0]), "+f"(c[1]), "+f"(c[2]), "+f"(c[3])
                 : "r"(a[0]), "r"(a[1]), "r"(a[2]), "r"(a[3]), "r"(b0), "r"(b1));
}

#define SM_XH 0u
#define SM_XL 32768u
#define SM_WH 65536u
#define SM_WL 98304u
#define SM_SB 131072u
#define SM_TOTAL (131072u + 512u)

__global__ __launch_bounds__(256, 1)
void k_sim(const float* __restrict__ x, const float* __restrict__ mask,
           const float* __restrict__ w_p)
{
    extern __shared__ unsigned char smem[];
    const int tid = threadIdx.x;
    const int r0  = blockIdx.x * 128;
    const int t   = r0 >> 11;          // r0 / 2048
    const int b0  = r0 & 2047;

    if (tid < 128) ((float*)(smem + SM_SB))[tid] = 0.f;

    // ---- load + convert X tile: 128 rows x 128 f32 -> bf16 hi/lo (swizzled)
    for (int i = tid; i < 2048; i += 256) {
        int m = i >> 4, g = i & 15;
        const float* p = x + (size_t)(r0 + m) * H_DIM + g * 8;
        float4 v0 = *(const float4*)p;
        float4 v1 = *(const float4*)(p + 4);
        float vv[8] = {v0.x, v0.y, v0.z, v0.w, v1.x, v1.y, v1.z, v1.w};
        unsigned hp[4], lp[4];
#pragma unroll
        for (int k2 = 0; k2 < 4; ++k2) {
            __nv_bfloat16 h0 = __float2bfloat16(vv[2*k2+0]);
            __nv_bfloat16 h1 = __float2bfloat16(vv[2*k2+1]);
            __nv_bfloat16 l0 = __float2bfloat16(vv[2*k2+0] - __bfloat162float(h0));
            __nv_bfloat16 l1 = __float2bfloat16(vv[2*k2+1] - __bfloat162float(h1));
            hp[k2] = ((unsigned)__bfloat16_as_ushort(h1) << 16) | (unsigned)__bfloat16_as_ushort(h0);
            lp[k2] = ((unsigned)__bfloat16_as_ushort(l1) << 16) | (unsigned)__bfloat16_as_ushort(l0);
        }
        unsigned off = (unsigned)m * 256u + ((unsigned)(g ^ (m & 7)) << 4);
        *(uint4*)(smem + SM_XH + off) = make_uint4(hp[0], hp[1], hp[2], hp[3]);
        *(uint4*)(smem + SM_XL + off) = make_uint4(lp[0], lp[1], lp[2], lp[3]);
    }
    // ---- load W^T bf16 tiles (pre-split in global, swizzled on STS)
    for (int i = tid; i < 2048; i += 256) {
        int d = i >> 4, g = i & 15;
        unsigned off = (unsigned)d * 256u + ((unsigned)(g ^ (d & 7)) << 4);
        *(uint4*)(smem + SM_WH + off) = *(const uint4*)(g_wkh + d * H_DIM + g * 8);
        *(uint4*)(smem + SM_WL + off) = *(const uint4*)(g_wkl + d * H_DIM + g * 8);
    }
    __syncthreads();

    const int warp = tid >> 5, lane = tid & 31;
    const int wm = warp & 3, wn = warp >> 2;        // 4 (m) x 2 (n) warp grid
    const int q  = lane >> 3, l7 = lane & 7;

    int rowA[2], rxa[2];
#pragma unroll
    for (int mi = 0; mi < 2; ++mi) {
        rowA[mi] = wm * 32 + mi * 16 + (q & 1) * 8 + l7;
        rxa[mi]  = rowA[mi] & 7;
    }
    const int gao = q >> 1;
    int rowB[4], rxb[4];
#pragma unroll
    for (int p = 0; p < 4; ++p) {
        rowB[p] = wn * 64 + p * 16 + (q >> 1) * 8 + l7;
        rxb[p]  = rowB[p] & 7;
    }
    const int gbo = q & 1;

    const unsigned xh_b = (unsigned)__cvta_generic_to_shared(smem + SM_XH);
    const unsigned xl_b = (unsigned)__cvta_generic_to_shared(smem + SM_XL);
    const unsigned wh_b = (unsigned)__cvta_generic_to_shared(smem + SM_WH);
    const unsigned wl_b = (unsigned)__cvta_generic_to_shared(smem + SM_WL);

    float acc[2][8][4];
#pragma unroll
    for (int mi = 0; mi < 2; ++mi)
#pragma unroll
        for (int j = 0; j < 8; ++j)
#pragma unroll
            for (int c = 0; c < 4; ++c) acc[mi][j][c] = 0.f;

#pragma unroll
    for (int ks = 0; ks < 8; ++ks) {
        unsigned ah[2][4], al[2][4], bh[4][4], bl[4][4];
#pragma unroll
        for (int mi = 0; mi < 2; ++mi) {
            unsigned off = (unsigned)rowA[mi] * 256u +
                           ((unsigned)((ks * 2 + gao) ^ rxa[mi]) << 4);
            ldsm4(ah[mi][0], ah[mi][1], ah[mi][2], ah[mi][3], xh_b + off);
            ldsm4(al[mi][0], al[mi][1], al[mi][2], al[mi][3], xl_b + off);
        }
#pragma unroll
        for (int p = 0; p < 4; ++p) {
            unsigned off = (unsigned)rowB[p] * 256u +
                           ((unsigned)((ks * 2 + gbo) ^ rxb[p]) << 4);
            ldsm4(bh[p][0], bh[p][1], bh[p][2], bh[p][3], wh_b + off);
            ldsm4(bl[p][0], bl[p][1], bl[p][2], bl[p][3], wl_b + off);
        }
#pragma unroll
        for (int mi = 0; mi < 2; ++mi)
#pragma unroll
            for (int j = 0; j < 8; ++j) {
                int p = j >> 1, o = (j & 1) * 2;
                mma_bf16(acc[mi][j], ah[mi], bh[p][o], bh[p][o + 1]);
                mma_bf16(acc[mi][j], ah[mi], bl[p][o], bl[p][o + 1]);
                mma_bf16(acc[mi][j], al[mi], bh[p][o], bh[p][o + 1]);
            }
    }

    // ---- epilogue: sigmoid(mask*key + query) . w_p  -> per-row reduce
    float* simbuf = (float*)(smem + SM_SB);
    const int g8 = lane >> 2, th = lane & 3;
    const float* qv = g_query;
#pragma unroll
    for (int mi = 0; mi < 2; ++mi) {
#pragma unroll
        for (int half = 0; half < 2; ++half) {
            int row = wm * 32 + mi * 16 + g8 + half * 8;
            int b   = b0 + row;
            float mval = __ldg(mask + t * B_DIM + b);
            const float* qrow = qv + b * H_DIM;
            float partial = 0.f;
#pragma unroll
            for (int j = 0; j < 8; ++j) {
#pragma unroll
                for (int c = 0; c < 2; ++c) {
                    int col   = wn * 64 + j * 8 + th * 2 + c;
                    float key = acc[mi][j][half * 2 + c];
                    float arg = fmaf(mval, key, __ldg(qrow + col));
                    float sg  = __fdividef(1.f, 1.f + __expf(-arg));
                    partial   = fmaf(sg, __ldg(w_p + t * H_DIM + col), partial);
                }
            }
            partial += __shfl_xor_sync(0xffffffffu, partial, 1);
            partial += __shfl_xor_sync(0xffffffffu, partial, 2);
            if (th == 0) atomicAdd(&simbuf[row], partial);
        }
    }
    __syncthreads();
    if (tid < 128) g_sim[r0 + tid] = simbuf[tid];
}

// ---------------------------------------------------------------------------
// K4: per-b masked softmax (no max needed, |sim|<=16) + weighted x reduction
//     out[b][h] = sum_t (mask*e^{sim}) * x[t][b][h] / sum_t (mask*e^{sim})
// ---------------------------------------------------------------------------
__global__ void k_out(const float* __restrict__ x, const float* __restrict__ mask,
                      float* __restrict__ out)
{
    __shared__ float als[T_DIM];
    __shared__ float red[128];
    const int b = blockIdx.x, tid = threadIdx.x;

    float zp = 0.f;
    for (int t = tid; t < T_DIM; t += 128) {
        float a = mask[t * B_DIM + b] * __expf(g_sim[t * B_DIM + b]);
        als[t] = a;
        zp += a;
    }
    red[tid] = zp;
    __syncthreads();
    for (int s = 64; s > 0; s >>= 1) {
        if (tid < s) red[tid] += red[tid + s];
        __syncthreads();
    }
    float invZ = __fdividef(1.f, red[0]);

    float acc = 0.f;
    const float* xp = x + (size_t)b * H_DIM + tid;
#pragma unroll 4
    for (int t = 0; t < T_DIM; ++t)
        acc = fmaf(als[t], xp[(size_t)t * BH], acc);
    out[b * H_DIM + tid] = acc * invZ;
}

// ---------------------------------------------------------------------------
extern "C" void kernel_launch(void* const* d_in, const int* in_sizes, int n_in,
                              void* d_out, int out_size)
{
    const float* x    = (const float*)d_in[0];   // [T,B,H]
    const float* mask = (const float*)d_in[1];   // [T,B]
    const float* w_p  = (const float*)d_in[2];   // [T,H]
    const float* w_k  = (const float*)d_in[3];   // [H,H]
    const float* w_q  = (const float*)d_in[4];   // [H,H]
    float* out = (float*)d_out;                  // [B,H]

    cudaFuncSetAttribute(k_sim, cudaFuncAttributeMaxDynamicSharedMemorySize,
                         (int)SM_TOTAL);

    k_mean <<<BH / 256, 256>>>(x, mask);
    k_wconv<<<64, 256>>>(w_k);
    k_query<<<B_DIM / 8, 256>>>(w_q);
    k_sim  <<<TB / 128, 256, SM_TOTAL>>>(x, mask, w_p);
    k_out  <<<B_DIM, 128>>>(x, mask, out);
}

// round 3
// speedup vs baseline: 1.4923x; 1.4923x over previous
#include <cuda_runtime.h>
#include <cuda_bf16.h>
#include <cstdint>

#define T_DIM 200
#define B_DIM 2048
#define H_DIM 128
#define TB (T_DIM*B_DIM)      /* 409600 */
#define BH (B_DIM*H_DIM)      /* 262144 */
#define NT_CHUNKS 9

// ---------------- scratch (device globals: no allocation allowed) ----------
__device__ float g_mean[BH];
__device__ float g_query[BH];
__device__ __nv_bfloat16 g_wkh[H_DIM*H_DIM];   // w_k^T hi  [d][h]
__device__ __nv_bfloat16 g_wkl[H_DIM*H_DIM];   // w_k^T lo  [d][h]
__device__ __nv_bfloat16 g_xh[(size_t)TB*H_DIM];  // x hi bf16
__device__ __nv_bfloat16 g_xl[(size_t)TB*H_DIM];  // x lo bf16
__device__ float g_sim[TB];                    // sim[t][b]

// ---------------------------------------------------------------------------
// K1: masked mean over t  +  fused x -> bf16 hi/lo split (written once)
// ---------------------------------------------------------------------------
__global__ void k_prep(const float* __restrict__ x, const float* __restrict__ mask)
{
    int idx = blockIdx.x * 256 + threadIdx.x;   // [0, BH/2)
    int j = idx * 2;
    int b = j >> 7;
    float a0 = 0.f, a1 = 0.f;
#pragma unroll 4
    for (int t = 0; t < T_DIM; ++t) {
        float2 v = *(const float2*)(x + (size_t)t * BH + j);
        float m = __ldg(mask + t * B_DIM + b);
        a0 = fmaf(v.x, m, a0);
        a1 = fmaf(v.y, m, a1);
        __nv_bfloat16 h0 = __float2bfloat16(v.x);
        __nv_bfloat16 h1 = __float2bfloat16(v.y);
        __nv_bfloat162 hh; hh.x = h0; hh.y = h1;
        *(__nv_bfloat162*)(g_xh + (size_t)t * BH + j) = hh;
        __nv_bfloat162 ll;
        ll.x = __float2bfloat16(v.x - __bfloat162float(h0));
        ll.y = __float2bfloat16(v.y - __bfloat162float(h1));
        *(__nv_bfloat162*)(g_xl + (size_t)t * BH + j) = ll;
    }
    g_mean[j]     = a0;
    g_mean[j + 1] = a1;
}

// ---------------------------------------------------------------------------
// K2a: w_k -> transposed bf16 hi/lo (tiny, once)
// ---------------------------------------------------------------------------
__global__ void k_wconv(const float* __restrict__ w_k)
{
    int i = blockIdx.x * 256 + threadIdx.x;
    int h = i >> 7, d = i & 127;
    float v = w_k[i];
    __nv_bfloat16 hi = __float2bfloat16(v);
    g_wkh[d * H_DIM + h] = hi;
    g_wkl[d * H_DIM + h] = __float2bfloat16(v - __bfloat162float(hi));
}

// ---------------------------------------------------------------------------
// K2b: query[b][d] = sum_h mean[b][h] * w_q[h][d]
// ---------------------------------------------------------------------------
__global__ void k_query(const float* __restrict__ w_q)
{
    __shared__ float sm[8][128];
    int b0 = blockIdx.x * 8;
    int tid = threadIdx.x;
    for (int i = tid; i < 1024; i += 256)
        sm[i >> 7][i & 127] = g_mean[b0 * H_DIM + i];
    __syncthreads();
    int d = tid & 127, half = tid >> 7;
    float a0 = 0.f, a1 = 0.f, a2 = 0.f, a3 = 0.f;
#pragma unroll 4
    for (int h = 0; h < 128; ++h) {
        float wv = __ldg(w_q + h * H_DIM + d);
        a0 = fmaf(sm[half * 4 + 0][h], wv, a0);
        a1 = fmaf(sm[half * 4 + 1][h], wv, a1);
        a2 = fmaf(sm[half * 4 + 2][h], wv, a2);
        a3 = fmaf(sm[half * 4 + 3][h], wv, a3);
    }
    g_query[(b0 + half * 4 + 0) * H_DIM + d] = a0;
    g_query[(b0 + half * 4 + 1) * H_DIM + d] = a1;
    g_query[(b0 + half * 4 + 2) * H_DIM + d] = a2;
    g_query[(b0 + half * 4 + 3) * H_DIM + d] = a3;
}

// ---------------------------------------------------------------------------
// K3: sim kernel — persistent b-block, W loaded once, X double-buffered cp.async
// ---------------------------------------------------------------------------
__device__ __forceinline__ void ldsm4(unsigned &r0, unsigned &r1,
                                      unsigned &r2, unsigned &r3, unsigned addr)
{
    asm volatile("ldmatrix.sync.aligned.m8n8.x4.shared.b16 {%0,%1,%2,%3}, [%4];"
                 : "=r"(r0), "=r"(r1), "=r"(r2), "=r"(r3) : "r"(addr));
}
__device__ __forceinline__ void mma_bf16(float *c, const unsigned *a,
                                         unsigned b0, unsigned b1)
{
    asm volatile("mma.sync.aligned.m16n8k16.row.col.f32.bf16.bf16.f32 "
                 "{%0,%1,%2,%3},{%4,%5,%6,%7},{%8,%9},{%0,%1,%2,%3};"
                 : "+f"(c[0]), "+f"(c[1]), "+f"(c[2]), "+f"(c[3])
                 : "r"(a[0]), "r"(a[1]), "r"(a[2]), "r"(a[3]), "r"(b0), "r"(b1));
}
__device__ __forceinline__ void cp16(unsigned dst, const void* src)
{
    asm volatile("cp.async.cg.shared.global [%0], [%1], 16;" :: "r"(dst), "l"(src));
}
#define CP_COMMIT asm volatile("cp.async.commit_group;")
#define CP_WAIT1  asm volatile("cp.async.wait_group 1;")

#define SM_WH 0u
#define SM_WL 32768u
#define SM_XB 65536u          /* two 64KB X buffers (hi 32KB + lo 32KB each) */
#define SM_P  196608u         /* 2 x 128 float partials */
#define SM_TOTAL 197632u

__device__ __forceinline__ void load_x_tile(unsigned bufbase, int t, int b0, int tid)
{
    const __nv_bfloat16* srcH = g_xh + ((size_t)t * B_DIM + b0) * H_DIM;
    const __nv_bfloat16* srcL = g_xl + ((size_t)t * B_DIM + b0) * H_DIM;
#pragma unroll
    for (int i = tid; i < 2048; i += 256) {
        int m = i >> 4, g = i & 15;
        unsigned off = (unsigned)m * 256u + ((unsigned)(g ^ (m & 7)) << 4);
        cp16(bufbase + off,          srcH + m * H_DIM + g * 8);
        cp16(bufbase + 32768u + off, srcL + m * H_DIM + g * 8);
    }
}

__global__ __launch_bounds__(256, 1)
void k_sim(const float* __restrict__ mask, const float* __restrict__ w_p)
{
    extern __shared__ unsigned char smem[];
    const unsigned sbase = (unsigned)__cvta_generic_to_shared(smem);
    const int tid = threadIdx.x;
    const int bb  = blockIdx.x / NT_CHUNKS;
    const int c   = blockIdx.x % NT_CHUNKS;
    const int b0  = bb * 128;
    const int t0  = (c * T_DIM) / NT_CHUNKS;
    const int t1  = ((c + 1) * T_DIM) / NT_CHUNKS;
    const int nt  = t1 - t0;

    // ---- group 0: W tiles (swizzled) + X tile 0
#pragma unroll
    for (int i = tid; i < 2048; i += 256) {
        int d = i >> 4, g = i & 15;
        unsigned off = (unsigned)d * 256u + ((unsigned)(g ^ (d & 7)) << 4);
        cp16(sbase + SM_WH + off, g_wkh + d * H_DIM + g * 8);
        cp16(sbase + SM_WL + off, g_wkl + d * H_DIM + g * 8);
    }
    load_x_tile(sbase + SM_XB, t0, b0, tid);
    CP_COMMIT;
    // ---- group 1: X tile 1
    if (nt > 1) load_x_tile(sbase + SM_XB + 65536u, t0 + 1, b0, tid);
    CP_COMMIT;
    CP_WAIT1;
    __syncthreads();

    const int warp = tid >> 5, lane = tid & 31;
    const int wm = warp & 3, wn = warp >> 2;
    const int q  = lane >> 3, l7 = lane & 7;
    const int g8 = lane >> 2, th = lane & 3;

    int rowA[2], rxa[2];
#pragma unroll
    for (int mi = 0; mi < 2; ++mi) {
        rowA[mi] = wm * 32 + mi * 16 + (q & 1) * 8 + l7;
        rxa[mi]  = rowA[mi] & 7;
    }
    const int gao = q >> 1;
    int rowB[4], rxb[4];
#pragma unroll
    for (int p = 0; p < 4; ++p) {
        rowB[p] = wn * 64 + p * 16 + (q >> 1) * 8 + l7;
        rxb[p]  = rowB[p] & 7;
    }
    const int gbo = q & 1;

    const unsigned wh_b = sbase + SM_WH;
    const unsigned wl_b = sbase + SM_WL;
    float* part = (float*)(smem + SM_P);

    for (int it = 0; it < nt; ++it) {
        const int t = t0 + it;
        const unsigned xh_b = sbase + SM_XB + (unsigned)(it & 1) * 65536u;
        const unsigned xl_b = xh_b + 32768u;

        float acc[2][8][4];
#pragma unroll
        for (int mi = 0; mi < 2; ++mi)
#pragma unroll
            for (int j = 0; j < 8; ++j)
#pragma unroll
                for (int cc = 0; cc < 4; ++cc) acc[mi][j][cc] = 0.f;

#pragma unroll
        for (int ks = 0; ks < 8; ++ks) {
            unsigned ah[2][4], al[2][4], bh[4][4], bl[4][4];
#pragma unroll
            for (int mi = 0; mi < 2; ++mi) {
                unsigned off = (unsigned)rowA[mi] * 256u +
                               ((unsigned)((ks * 2 + gao) ^ rxa[mi]) << 4);
                ldsm4(ah[mi][0], ah[mi][1], ah[mi][2], ah[mi][3], xh_b + off);
                ldsm4(al[mi][0], al[mi][1], al[mi][2], al[mi][3], xl_b + off);
            }
#pragma unroll
            for (int p = 0; p < 4; ++p) {
                unsigned off = (unsigned)rowB[p] * 256u +
                               ((unsigned)((ks * 2 + gbo) ^ rxb[p]) << 4);
                ldsm4(bh[p][0], bh[p][1], bh[p][2], bh[p][3], wh_b + off);
                ldsm4(bl[p][0], bl[p][1], bl[p][2], bl[p][3], wl_b + off);
            }
#pragma unroll
            for (int mi = 0; mi < 2; ++mi)
#pragma unroll
                for (int j = 0; j < 8; ++j) {
                    int p = j >> 1, o = (j & 1) * 2;
                    mma_bf16(acc[mi][j], ah[mi], bh[p][o], bh[p][o + 1]);
                    mma_bf16(acc[mi][j], ah[mi], bl[p][o], bl[p][o + 1]);
                    mma_bf16(acc[mi][j], al[mi], bh[p][o], bh[p][o + 1]);
                }
        }

        // ---- epilogue: sigmoid(mask*key + query) . w_p -> per-row partials
        float wp[16];
        {
            const float* wrow = w_p + t * H_DIM + wn * 64;
#pragma unroll
            for (int j = 0; j < 8; ++j) {
                float2 v = __ldg((const float2*)(wrow + j * 8 + th * 2));
                wp[j * 2]     = v.x;
                wp[j * 2 + 1] = v.y;
            }
        }
#pragma unroll
        for (int mi = 0; mi < 2; ++mi) {
#pragma unroll
            for (int half = 0; half < 2; ++half) {
                int row = wm * 32 + mi * 16 + half * 8 + g8;
                int b   = b0 + row;
                float mval = __ldg(mask + t * B_DIM + b);
                const float* qrow = g_query + b * H_DIM + wn * 64;
                float partial = 0.f;
#pragma unroll
                for (int j = 0; j < 8; ++j) {
                    float2 q2 = __ldg((const float2*)(qrow + j * 8 + th * 2));
                    {
                        float arg = fmaf(mval, acc[mi][j][half * 2 + 0], q2.x);
                        float sg  = __fdividef(1.f, 1.f + __expf(-arg));
                        partial   = fmaf(sg, wp[j * 2 + 0], partial);
                    }
                    {
                        float arg = fmaf(mval, acc[mi][j][half * 2 + 1], q2.y);
                        float sg  = __fdividef(1.f, 1.f + __expf(-arg));
                        partial   = fmaf(sg, wp[j * 2 + 1], partial);
                    }
                }
                partial += __shfl_xor_sync(0xffffffffu, partial, 1);
                partial += __shfl_xor_sync(0xffffffffu, partial, 2);
                if (th == 0) part[wn * 128 + row] = partial;
            }
        }
        __syncthreads();
        if (tid < 128)
            g_sim[t * B_DIM + b0 + tid] = part[tid] + part[128 + tid];

        // prefetch tile it+2 into the buffer we just finished reading
        if (it + 2 < nt)
            load_x_tile(sbase + SM_XB + (unsigned)(it & 1) * 65536u, t0 + it + 2, b0, tid);
        CP_COMMIT;
        CP_WAIT1;
        __syncthreads();
    }
}

// ---------------------------------------------------------------------------
// K4: per-b masked softmax (|sim|<=16, no max needed) + weighted x reduction
// ---------------------------------------------------------------------------
__global__ void k_out(const float* __restrict__ x, const float* __restrict__ mask,
                      float* __restrict__ out)
{
    __shared__ float als[T_DIM];
    __shared__ float red[128];
    const int b = blockIdx.x, tid = threadIdx.x;

    float zp = 0.f;
    for (int t = tid; t < T_DIM; t += 128) {
        float a = mask[t * B_DIM + b] * __expf(g_sim[t * B_DIM + b]);
        als[t] = a;
        zp += a;
    }
    red[tid] = zp;
    __syncthreads();
    for (int s = 64; s > 0; s >>= 1) {
        if (tid < s) red[tid] += red[tid + s];
        __syncthreads();
    }
    float invZ = __fdividef(1.f, red[0]);

    float acc = 0.f;
    const float* xp = x + (size_t)b * H_DIM + tid;
#pragma unroll 4
    for (int t = 0; t < T_DIM; ++t)
        acc = fmaf(als[t], xp[(size_t)t * BH], acc);
    out[b * H_DIM + tid] = acc * invZ;
}

// ---------------------------------------------------------------------------
extern "C" void kernel_launch(void* const* d_in, const int* in_sizes, int n_in,
                              void* d_out, int out_size)
{
    const float* x    = (const float*)d_in[0];
    const float* mask = (const float*)d_in[1];
    const float* w_p  = (const float*)d_in[2];
    const float* w_k  = (const float*)d_in[3];
    const float* w_q  = (const float*)d_in[4];
    float* out = (float*)d_out;

    cudaFuncSetAttribute(k_sim, cudaFuncAttributeMaxDynamicSharedMemorySize,
                         (int)SM_TOTAL);

    k_prep <<<BH / 512, 256>>>(x, mask);
    k_wconv<<<64, 256>>>(w_k);
    k_query<<<B_DIM / 8, 256>>>(w_q);
    k_sim  <<<16 * NT_CHUNKS, 256, SM_TOTAL>>>(mask, w_p);
    k_out  <<<B_DIM, 128>>>(x, mask, out);
}